// round 14
// baseline (speedup 1.0000x reference)
#include <cuda_runtime.h>
#include <cuda_bf16.h>
#include <cstddef>
#include <cstdint>

#define BB 8
#define CC 256
#define NN 4096            // tokens
#define GG 32
#define CPG 8

// ---------------- scratch (device globals: allocation-free) ----------------
__device__ float g_h[(size_t)BB * CC * NN];                     // normalized input (fp32)
__device__ __nv_bfloat16 g_ht[(size_t)BB * NN * CC];            // h^T bf16 [b][n][c]
__device__ __nv_bfloat16 g_wq[768 * 256];                       // qkv_w bf16
__device__ __nv_bfloat16 g_wp[256 * 256];                       // proj_w bf16
__device__ __nv_bfloat16 g_qb[(size_t)BB * NN * CC];            // Q [b][q][c] (scaled)
__device__ __nv_bfloat16 g_kb[(size_t)BB * NN * CC];            // K [b][k][c]
__device__ __nv_bfloat16 g_vb[(size_t)BB * CC * NN];            // V [b][c][k]
__device__ __nv_bfloat16 g_ob[(size_t)BB * NN * CC];            // attn out [b][n][c]

// ============================ helpers =======================================
__device__ __forceinline__ uint32_t smem_u32(const void* p) {
    uint32_t a;
    asm("{ .reg .u64 t; cvta.to.shared.u64 t, %1; cvt.u32.u64 %0, t; }"
        : "=r"(a) : "l"(p));
    return a;
}
__device__ __forceinline__ uint32_t pack_bf16x2(float lo, float hi) {
    uint32_t r;
    asm("cvt.rn.bf16x2.f32 %0, %1, %2;" : "=r"(r) : "f"(hi), "f"(lo));
    return r;
}
__device__ __forceinline__ float ex2f(float x) {
    float r;
    asm("ex2.approx.ftz.f32 %0, %1;" : "=f"(r) : "f"(x));
    return r;
}
__device__ __forceinline__ void ldsm_x4(uint32_t& r0, uint32_t& r1,
                                        uint32_t& r2, uint32_t& r3, uint32_t a) {
    asm volatile("ldmatrix.sync.aligned.m8n8.x4.shared.b16 {%0,%1,%2,%3}, [%4];"
                 : "=r"(r0), "=r"(r1), "=r"(r2), "=r"(r3) : "r"(a));
}
__device__ __forceinline__ void mma_bf16(float4& d,
                                         uint32_t a0, uint32_t a1, uint32_t a2, uint32_t a3,
                                         uint32_t b0, uint32_t b1) {
    asm volatile(
        "mma.sync.aligned.m16n8k16.row.col.f32.bf16.bf16.f32 "
        "{%0,%1,%2,%3}, {%4,%5,%6,%7}, {%8,%9}, {%0,%1,%2,%3};"
        : "+f"(d.x), "+f"(d.y), "+f"(d.z), "+f"(d.w)
        : "r"(a0), "r"(a1), "r"(a2), "r"(a3), "r"(b0), "r"(b1));
}
#define CP_ASYNC16(dst, src) \
    asm volatile("cp.async.cg.shared.global [%0], [%1], 16;" \
                 :: "r"(dst), "l"(src) : "memory")
#define CP_COMMIT() asm volatile("cp.async.commit_group;" ::: "memory")
#define CP_WAIT(n)  asm volatile("cp.async.wait_group %0;" :: "n"(n) : "memory")

// ============================ GroupNorm =====================================
__global__ void __launch_bounds__(256) gn_kernel(const float* __restrict__ x,
                                                 const float* __restrict__ w,
                                                 const float* __restrict__ bg,
                                                 float* __restrict__ h)
{
    const int g = blockIdx.x, b = blockIdx.y;
    const size_t base = ((size_t)b * CC + (size_t)g * CPG) * NN;
    const float* xp = x + base;
    float* hp = h + base;
    const int tid = threadIdx.x;

    float s = 0.f, ss = 0.f;
#pragma unroll
    for (int t = 0; t < 32; t++) {
        float4 v = *reinterpret_cast<const float4*>(xp + (size_t)(t * 256 + tid) * 4);
        s  += v.x + v.y + v.z + v.w;
        ss += v.x * v.x + v.y * v.y + v.z * v.z + v.w * v.w;
    }
#pragma unroll
    for (int o = 16; o; o >>= 1) {
        s  += __shfl_xor_sync(0xffffffffu, s, o);
        ss += __shfl_xor_sync(0xffffffffu, ss, o);
    }
    __shared__ float rs[8], rss[8], stats[2];
    if ((tid & 31) == 0) { rs[tid >> 5] = s; rss[tid >> 5] = ss; }
    __syncthreads();
    if (tid == 0) {
        float ts = 0.f, tss = 0.f;
#pragma unroll
        for (int i = 0; i < 8; i++) { ts += rs[i]; tss += rss[i]; }
        const float inv_n = 1.0f / (CPG * NN);
        float mu = ts * inv_n;
        float var = tss * inv_n - mu * mu;
        stats[0] = mu;
        stats[1] = rsqrtf(var + 1e-5f);
    }
    __syncthreads();
    const float mu = stats[0], rsg = stats[1];
#pragma unroll
    for (int t = 0; t < 32; t++) {
        const int idx = (t * 256 + tid) * 4;
        const int c = g * CPG + (idx >> 12);
        const float sc = w[c] * rsg;
        const float sh = bg[c] - mu * sc;
        float4 v = *reinterpret_cast<const float4*>(xp + idx);
        v.x = v.x * sc + sh; v.y = v.y * sc + sh;
        v.z = v.z * sc + sh; v.w = v.w * sc + sh;
        *reinterpret_cast<float4*>(hp + idx) = v;
    }
}

// =================== weight fp32 -> bf16 convert ============================
__global__ void __launch_bounds__(256) wconv_kernel(const float* __restrict__ qkvw,
                                                    const float* __restrict__ projw,
                                                    __nv_bfloat16* __restrict__ wq,
                                                    __nv_bfloat16* __restrict__ wp)
{
    int idx = blockIdx.x * 256 + threadIdx.x;
    if (idx < 768 * 256) wq[idx] = __float2bfloat16(qkvw[idx]);
    else                 wp[idx - 768 * 256] = __float2bfloat16(projw[idx - 768 * 256]);
}

// ========== h fp32 [b][c][n] -> bf16 [b][n][c] transpose ====================
__global__ void __launch_bounds__(256) ht_kernel(const float* __restrict__ h,
                                                 __nv_bfloat16* __restrict__ ht)
{
    __shared__ float tile[32][33];
    const int b = blockIdx.z;
    const int n0 = blockIdx.x * 32, c0 = blockIdx.y * 32;
    const int tx = threadIdx.x & 31, ty = threadIdx.x >> 5;   // 32 x 8

    const float* src = h + (size_t)b * CC * NN;
#pragma unroll
    for (int i = 0; i < 4; i++) {
        int c = c0 + ty + i * 8;
        tile[ty + i * 8][tx] = src[(size_t)c * NN + n0 + tx];
    }
    __syncthreads();
#pragma unroll
    for (int i = 0; i < 4; i++) {
        int n = n0 + ty + i * 8;
        ht[((size_t)b * NN + n) * CC + c0 + tx] = __float2bfloat16(tile[tx][ty + i * 8]);
    }
}

// ================= bf16 tensor GEMM (qkv mode 0 / proj mode 1) ==============
#define TG_ST  528                       // 256 bf16 + 16B pad
#define TG_SA  0
#define TG_SB  (64 * TG_ST)              // 33792
#define TG_SMEM ((64 + 128) * TG_ST)     // 101376

__global__ void __launch_bounds__(256) tgemm_kernel(const __nv_bfloat16* __restrict__ A,
                                                    const __nv_bfloat16* __restrict__ Bm,
                                                    const float* __restrict__ bias,
                                                    const float* __restrict__ resid,
                                                    __nv_bfloat16* __restrict__ oq,
                                                    __nv_bfloat16* __restrict__ ok,
                                                    __nv_bfloat16* __restrict__ ov,
                                                    float* __restrict__ ofp,
                                                    int mode)
{
    extern __shared__ char sm[];
    const uint32_t sbase = smem_u32(sm);
    const int tid  = threadIdx.x;
    const int lane = tid & 31;
    const int wid  = tid >> 5;
    const int g    = lane >> 2;
    const int t    = lane & 3;
    const int n0   = blockIdx.x * 128;
    const int m0   = blockIdx.y * 64;
    const int b    = blockIdx.z;

    const __nv_bfloat16* Bb = Bm + (size_t)b * NN * CC;

#pragma unroll
    for (int tt = 0; tt < 8; tt++) {
        int idx = tid + tt * 256;
        int r = idx >> 5, ch = idx & 31;
        CP_ASYNC16(sbase + TG_SA + r * TG_ST + ch * 16,
                   A + (size_t)(m0 + r) * 256 + ch * 8);
    }
#pragma unroll
    for (int tt = 0; tt < 16; tt++) {
        int idx = tid + tt * 256;
        int r = idx >> 5, ch = idx & 31;
        CP_ASYNC16(sbase + TG_SB + r * TG_ST + ch * 16,
                   Bb + (size_t)(n0 + r) * 256 + ch * 8);
    }
    CP_COMMIT();
    CP_WAIT(0);
    __syncthreads();

    const int wm = (wid & 3) * 16;
    const int wn = (wid >> 2) * 64;
    const int lrow = ((lane >> 3) & 1) * 8 + (lane & 7);
    const int loff = ((lane >> 4) & 1) * 16;
    const uint32_t aA = sbase + TG_SA + (wm + lrow) * TG_ST + loff;
    const uint32_t bB = sbase + TG_SB + (wn + lrow) * TG_ST + loff;

    float4 d[8];
#pragma unroll
    for (int j = 0; j < 8; j++) d[j] = make_float4(0.f, 0.f, 0.f, 0.f);

#pragma unroll 4
    for (int kc = 0; kc < 16; kc++) {
        uint32_t a0, a1, a2, a3;
        ldsm_x4(a0, a1, a2, a3, aA + kc * 32);
#pragma unroll
        for (int f = 0; f < 4; f++) {
            uint32_t b0, b1, b2, b3;
            ldsm_x4(b0, b1, b2, b3, bB + f * (16 * TG_ST) + kc * 32);
            mma_bf16(d[2 * f],     a0, a1, a2, a3, b0, b2);
            mma_bf16(d[2 * f + 1], a0, a1, a2, a3, b1, b3);
        }
    }

    const float bv0 = bias[m0 + wm + g];
    const float bv1 = bias[m0 + wm + g + 8];

    if (mode == 1) {
        const int o0 = m0 + wm + g, o1 = o0 + 8;
#pragma unroll
        for (int j = 0; j < 8; j++) {
            const int n = n0 + wn + (j >> 1) * 16 + (j & 1) * 8 + 2 * t;
            const float* r0p = resid + ((size_t)b * CC + o0) * NN + n;
            const float* r1p = resid + ((size_t)b * CC + o1) * NN + n;
            float2 rv0 = *reinterpret_cast<const float2*>(r0p);
            float2 rv1 = *reinterpret_cast<const float2*>(r1p);
            float2 w0 = make_float2(d[j].x + bv0 + rv0.x, d[j].y + bv0 + rv0.y);
            float2 w1 = make_float2(d[j].z + bv1 + rv1.x, d[j].w + bv1 + rv1.y);
            *reinterpret_cast<float2*>(ofp + ((size_t)b * CC + o0) * NN + n) = w0;
            *reinterpret_cast<float2*>(ofp + ((size_t)b * CC + o1) * NN + n) = w1;
        }
        return;
    }

    if (m0 >= 512) {
        const int o0 = m0 - 512 + wm + g, o1 = o0 + 8;
#pragma unroll
        for (int j = 0; j < 8; j++) {
            const int n = n0 + wn + (j >> 1) * 16 + (j & 1) * 8 + 2 * t;
            *reinterpret_cast<uint32_t*>(ov + ((size_t)b * CC + o0) * NN + n) =
                pack_bf16x2(d[j].x + bv0, d[j].y + bv0);
            *reinterpret_cast<uint32_t*>(ov + ((size_t)b * CC + o1) * NN + n) =
                pack_bf16x2(d[j].z + bv1, d[j].w + bv1);
        }
        return;
    }

    const float scl = (m0 < 256) ? 0.09016844f : 1.0f;    // log2(e)/16 for q
    __nv_bfloat16* sT = reinterpret_cast<__nv_bfloat16*>(sm);   // [128 n][72]
    __syncthreads();
    {
        const int m_lo = wm + g, m_hi = m_lo + 8;
#pragma unroll
        for (int j = 0; j < 8; j++) {
            const int n = wn + (j >> 1) * 16 + (j & 1) * 8 + 2 * t;
            sT[n * 72 + m_lo]       = __float2bfloat16((d[j].x + bv0) * scl);
            sT[(n + 1) * 72 + m_lo] = __float2bfloat16((d[j].y + bv0) * scl);
            sT[n * 72 + m_hi]       = __float2bfloat16((d[j].z + bv1) * scl);
            sT[(n + 1) * 72 + m_hi] = __float2bfloat16((d[j].w + bv1) * scl);
        }
    }
    __syncthreads();
    __nv_bfloat16* dst = (m0 < 256) ? oq : ok;
    const int mo = (m0 < 256) ? m0 : m0 - 256;
#pragma unroll
    for (int cidx = 0; cidx < 4; cidx++) {
        int idx = tid + cidx * 256;
        int n = idx >> 3, seg = idx & 7;
        uint4 v = *reinterpret_cast<uint4*>(sT + n * 72 + seg * 8);
        *reinterpret_cast<uint4*>(dst + ((size_t)b * NN + n0 + n) * CC + mo + seg * 8) = v;
    }
}

// ==== flash attention: 512 threads / 16 warps (4 per SMSP) ==================
// warp (qg = wid&7, ch = wid>>3): S = 16q x 64k (full, duplicated across the
// 2 ch-warps of a q-group), softmax as validated, O = 16q x 128c.
#define QSTB 528
#define VSTB 144
#define SQ_OFF 0
#define SK_OFF  (128 * QSTB)
#define SK_BUF  (64 * QSTB)
#define SV_OFF  (SK_OFF + 2 * SK_BUF)
#define SV_BUF  (256 * VSTB)
#define ATT_SMEM (SV_OFF + 2 * SV_BUF)     // 208896

__global__ void __launch_bounds__(512, 1) attn6_kernel(const __nv_bfloat16* __restrict__ qb,
                                                       const __nv_bfloat16* __restrict__ kb,
                                                       const __nv_bfloat16* __restrict__ vb,
                                                       __nv_bfloat16* __restrict__ ob)
{
    extern __shared__ char sm[];
    const uint32_t sbase = smem_u32(sm);

    const int tid  = threadIdx.x;
    const int lane = tid & 31;
    const int wid  = tid >> 5;             // 0..15
    const int qg   = wid & 7;              // q-group
    const int chg  = wid >> 3;             // channel half (0/1)
    const int b    = blockIdx.y;
    const int q0   = blockIdx.x * 128;

    const __nv_bfloat16* Qg = qb + ((size_t)b * NN + q0) * 256;
    const __nv_bfloat16* Kg = kb + (size_t)b * NN * 256;
    const __nv_bfloat16* Vg = vb + (size_t)b * CC * NN;

    // ---- load Q tile: [128][256] bf16 (4096 16B chunks / 512 thr = 8) ----
#pragma unroll
    for (int tt = 0; tt < 8; tt++) {
        int idx = tid + tt * 512;
        int r = idx >> 5, ch = idx & 31;
        *reinterpret_cast<uint4*>(sm + SQ_OFF + r * QSTB + ch * 16) =
            *reinterpret_cast<const uint4*>(Qg + (size_t)r * 256 + ch * 8);
    }

    // cp.async slices: K 2048 chunks (4/thr), V 2048 chunks (4/thr)
    const int kr = tid >> 5, kch = tid & 31;     // K rows kr + tt*16
    const int vc = tid >> 3, vch = tid & 7;      // V cols vc + tt*64

    {
        const uint32_t kd = sbase + SK_OFF;
        const uint32_t vd = sbase + SV_OFF;
#pragma unroll
        for (int tt = 0; tt < 4; tt++) {
            int r = kr + tt * 16;
            CP_ASYNC16(kd + r * QSTB + kch * 16, Kg + (size_t)r * 256 + kch * 8);
        }
#pragma unroll
        for (int tt = 0; tt < 4; tt++) {
            int c = vc + tt * 64;
            CP_ASYNC16(vd + c * VSTB + vch * 16, Vg + (size_t)c * NN + vch * 8);
        }
        CP_COMMIT();
    }

    const int lrow = ((lane >> 3) & 1) * 8 + (lane & 7);
    const int loff = ((lane >> 4) & 1) * 16;
    const uint32_t aQ = sbase + SQ_OFF + (qg * 16 + lrow) * QSTB + loff;

    float4 oacc[16];                        // 16q x 128c
#pragma unroll
    for (int j = 0; j < 16; j++) oacc[j] = make_float4(0.f, 0.f, 0.f, 0.f);
    float m0r = -1e30f, m1r = -1e30f, l0r = 0.f, l1r = 0.f;

    for (int kt = 0; kt < 64; kt++) {
        const int cur = kt & 1;
        if (kt < 63) {
            const int k0n = (kt + 1) * 64;
            const uint32_t kd = sbase + SK_OFF + (cur ^ 1) * SK_BUF;
            const uint32_t vd = sbase + SV_OFF + (cur ^ 1) * SV_BUF;
#pragma unroll
            for (int tt = 0; tt < 4; tt++) {
                int r = kr + tt * 16;
                CP_ASYNC16(kd + r * QSTB + kch * 16,
                           Kg + (size_t)(k0n + r) * 256 + kch * 8);
            }
#pragma unroll
            for (int tt = 0; tt < 4; tt++) {
                int c = vc + tt * 64;
                CP_ASYNC16(vd + c * VSTB + vch * 16,
                           Vg + (size_t)c * NN + k0n + vch * 8);
            }
            CP_COMMIT();
            CP_WAIT(1);
        } else {
            CP_WAIT(0);
        }
        __syncthreads();

        const uint32_t bK = sbase + SK_OFF + cur * SK_BUF + lrow * QSTB + loff;
        const uint32_t bV = sbase + SV_OFF + cur * SV_BUF + (chg * 128 + lrow) * VSTB + loff;

        // ---- S = Q K^T : 16q x 64k, K-dim 256 ----
        float4 d[8];
#pragma unroll
        for (int j = 0; j < 8; j++) d[j] = make_float4(0.f, 0.f, 0.f, 0.f);
#pragma unroll 4
        for (int kc = 0; kc < 16; kc++) {
            uint32_t a0, a1, a2, a3;
            ldsm_x4(a0, a1, a2, a3, aQ + kc * 32);
#pragma unroll
            for (int ng = 0; ng < 4; ng++) {
                uint32_t b0, b1, b2, b3;
                ldsm_x4(b0, b1, b2, b3, bK + ng * (16 * QSTB) + kc * 32);
                mma_bf16(d[2 * ng],     a0, a1, a2, a3, b0, b2);
                mma_bf16(d[2 * ng + 1], a0, a1, a2, a3, b1, b3);
            }
        }

        // ---- online softmax (log2 units) ----
        float nm0 = -1e30f, nm1 = -1e30f;
#pragma unroll
        for (int j = 0; j < 8; j++) {
            nm0 = fmaxf(nm0, fmaxf(d[j].x, d[j].y));
            nm1 = fmaxf(nm1, fmaxf(d[j].z, d[j].w));
        }
        nm0 = fmaxf(nm0, __shfl_xor_sync(0xffffffffu, nm0, 1));
        nm0 = fmaxf(nm0, __shfl_xor_sync(0xffffffffu, nm0, 2));
        nm1 = fmaxf(nm1, __shfl_xor_sync(0xffffffffu, nm1, 1));
        nm1 = fmaxf(nm1, __shfl_xor_sync(0xffffffffu, nm1, 2));
        nm0 = fmaxf(m0r, nm0);
        nm1 = fmaxf(m1r, nm1);
        const float al0 = ex2f(m0r - nm0);
        const float al1 = ex2f(m1r - nm1);
        m0r = nm0; m1r = nm1;

        uint32_t pa[4][4];
        float ls0 = 0.f, ls1 = 0.f;
#pragma unroll
        for (int kc = 0; kc < 4; kc++) {
            float p00 = ex2f(d[2 * kc].x - nm0), p01 = ex2f(d[2 * kc].y - nm0);
            float p02 = ex2f(d[2 * kc].z - nm1), p03 = ex2f(d[2 * kc].w - nm1);
            float p10 = ex2f(d[2 * kc + 1].x - nm0), p11 = ex2f(d[2 * kc + 1].y - nm0);
            float p12 = ex2f(d[2 * kc + 1].z - nm1), p13 = ex2f(d[2 * kc + 1].w - nm1);
            ls0 += (p00 + p01) + (p10 + p11);
            ls1 += (p02 + p03) + (p12 + p13);
            pa[kc][0] = pack_bf16x2(p00, p01);
            pa[kc][1] = pack_bf16x2(p02, p03);
            pa[kc][2] = pack_bf16x2(p10, p11);
            pa[kc][3] = pack_bf16x2(p12, p13);
        }
        l0r = l0r * al0 + ls0;
        l1r = l1r * al1 + ls1;

        if (!__all_sync(0xffffffffu, (al0 == 1.f) & (al1 == 1.f))) {
#pragma unroll
            for (int j = 0; j < 16; j++) {
                oacc[j].x *= al0; oacc[j].y *= al0;
                oacc[j].z *= al1; oacc[j].w *= al1;
            }
        }

        // ---- O += P V^T : 16q x 128c (this warp's channel half) ----
#pragma unroll 4
        for (int cg = 0; cg < 8; cg++) {
#pragma unroll
            for (int kc = 0; kc < 4; kc++) {
                uint32_t b0, b1, b2, b3;
                ldsm_x4(b0, b1, b2, b3, bV + cg * (16 * VSTB) + kc * 32);
                mma_bf16(oacc[2 * cg],     pa[kc][0], pa[kc][1], pa[kc][2], pa[kc][3], b0, b2);
                mma_bf16(oacc[2 * cg + 1], pa[kc][0], pa[kc][1], pa[kc][2], pa[kc][3], b1, b3);
            }
        }
        __syncthreads();
    }

    // ---- combine the 4 per-lane l partials of each row ----
    l0r += __shfl_xor_sync(0xffffffffu, l0r, 1);
    l0r += __shfl_xor_sync(0xffffffffu, l0r, 2);
    l1r += __shfl_xor_sync(0xffffffffu, l1r, 1);
    l1r += __shfl_xor_sync(0xffffffffu, l1r, 2);

    // ---- epilogue: O / l -> bf16 [b][n][c] ----
    const float inv0 = __frcp_rn(l0r);
    const float inv1 = __frcp_rn(l1r);
    const int g = lane >> 2, t = lane & 3;
    const int qr0 = q0 + qg * 16 + g;
    const int qr1 = qr0 + 8;
    __nv_bfloat16* r0p = ob + ((size_t)b * NN + qr0) * CC + chg * 128;
    __nv_bfloat16* r1p = ob + ((size_t)b * NN + qr1) * CC + chg * 128;
#pragma unroll
    for (int j = 0; j < 16; j++) {
        const int c = 8 * j + t * 2;
        *reinterpret_cast<uint32_t*>(r0p + c) =
            pack_bf16x2(oacc[j].x * inv0, oacc[j].y * inv0);
        *reinterpret_cast<uint32_t*>(r1p + c) =
            pack_bf16x2(oacc[j].z * inv1, oacc[j].w * inv1);
    }
}

// ================================ launch ====================================
extern "C" void kernel_launch(void* const* d_in, const int* in_sizes, int n_in,
                              void* d_out, int out_size)
{
    const float* x     = (const float*)d_in[0];
    const float* nw    = (const float*)d_in[1];
    const float* nb    = (const float*)d_in[2];
    const float* qkvw  = (const float*)d_in[3];
    const float* qkvb  = (const float*)d_in[4];
    const float* projw = (const float*)d_in[5];
    const float* projb = (const float*)d_in[6];
    float* out = (float*)d_out;

    float* hbuf;
    __nv_bfloat16 *htp, *wqp, *wpp, *qbp, *kbp, *vbp, *obp;
    cudaGetSymbolAddress((void**)&hbuf, g_h);
    cudaGetSymbolAddress((void**)&htp, g_ht);
    cudaGetSymbolAddress((void**)&wqp, g_wq);
    cudaGetSymbolAddress((void**)&wpp, g_wp);
    cudaGetSymbolAddress((void**)&qbp, g_qb);
    cudaGetSymbolAddress((void**)&kbp, g_kb);
    cudaGetSymbolAddress((void**)&vbp, g_vb);
    cudaGetSymbolAddress((void**)&obp, g_ob);

    cudaFuncSetAttribute(attn6_kernel, cudaFuncAttributeMaxDynamicSharedMemorySize,
                         ATT_SMEM);
    cudaFuncSetAttribute(tgemm_kernel, cudaFuncAttributeMaxDynamicSharedMemorySize,
                         TG_SMEM);

    gn_kernel<<<dim3(GG, BB), 256>>>(x, nw, nb, hbuf);
    wconv_kernel<<<(768 * 256 + 256 * 256) / 256, 256>>>(qkvw, projw, wqp, wpp);
    ht_kernel<<<dim3(NN / 32, CC / 32, BB), 256>>>(hbuf, htp);
    tgemm_kernel<<<dim3(NN / 128, 12, BB), 256, TG_SMEM>>>(
        wqp, htp, qkvb, nullptr, qbp, kbp, vbp, nullptr, 0);
    attn6_kernel<<<dim3(NN / 128, BB), 512, ATT_SMEM>>>(qbp, kbp, vbp, obp);
    tgemm_kernel<<<dim3(NN / 128, 4, BB), 256, TG_SMEM>>>(
        wpp, obp, projb, x, nullptr, nullptr, nullptr, out, 1);
}

// round 17
// speedup vs baseline: 1.1272x; 1.1272x over previous
#include <cuda_runtime.h>
#include <cuda_bf16.h>
#include <cstddef>
#include <cstdint>

#define BB 8
#define CC 256
#define NN 4096            // tokens
#define GG 32
#define CPG 8

// ---------------- scratch (device globals: allocation-free) ----------------
__device__ float g_h[(size_t)BB * CC * NN];                     // normalized input (fp32)
__device__ __nv_bfloat16 g_ht[(size_t)BB * NN * CC];            // h^T bf16 [b][n][c]
__device__ __nv_bfloat16 g_wq[768 * 256];                       // qkv_w bf16
__device__ __nv_bfloat16 g_wp[256 * 256];                       // proj_w bf16
__device__ __nv_bfloat16 g_qb[(size_t)BB * NN * CC];            // Q [b][q][c] (scaled)
__device__ __nv_bfloat16 g_kb[(size_t)BB * NN * CC];            // K [b][k][c]
__device__ __nv_bfloat16 g_vb[(size_t)BB * CC * NN];            // V [b][c][k]
__device__ __nv_bfloat16 g_ob[(size_t)BB * NN * CC];            // attn out [b][n][c]

// ============================ helpers =======================================
__device__ __forceinline__ uint32_t smem_u32(const void* p) {
    uint32_t a;
    asm("{ .reg .u64 t; cvta.to.shared.u64 t, %1; cvt.u32.u64 %0, t; }"
        : "=r"(a) : "l"(p));
    return a;
}
__device__ __forceinline__ uint32_t pack_bf16x2(float lo, float hi) {
    uint32_t r;
    asm("cvt.rn.bf16x2.f32 %0, %1, %2;" : "=r"(r) : "f"(hi), "f"(lo));
    return r;
}
__device__ __forceinline__ float ex2f(float x) {
    float r;
    asm("ex2.approx.ftz.f32 %0, %1;" : "=f"(r) : "f"(x));
    return r;
}
__device__ __forceinline__ void ldsm_x4(uint32_t& r0, uint32_t& r1,
                                        uint32_t& r2, uint32_t& r3, uint32_t a) {
    asm volatile("ldmatrix.sync.aligned.m8n8.x4.shared.b16 {%0,%1,%2,%3}, [%4];"
                 : "=r"(r0), "=r"(r1), "=r"(r2), "=r"(r3) : "r"(a));
}
__device__ __forceinline__ void mma_bf16(float4& d,
                                         uint32_t a0, uint32_t a1, uint32_t a2, uint32_t a3,
                                         uint32_t b0, uint32_t b1) {
    asm volatile(
        "mma.sync.aligned.m16n8k16.row.col.f32.bf16.bf16.f32 "
        "{%0,%1,%2,%3}, {%4,%5,%6,%7}, {%8,%9}, {%0,%1,%2,%3};"
        : "+f"(d.x), "+f"(d.y), "+f"(d.z), "+f"(d.w)
        : "r"(a0), "r"(a1), "r"(a2), "r"(a3), "r"(b0), "r"(b1));
}
#define CP_ASYNC16(dst, src) \
    asm volatile("cp.async.cg.shared.global [%0], [%1], 16;" \
                 :: "r"(dst), "l"(src) : "memory")
#define CP_COMMIT() asm volatile("cp.async.commit_group;" ::: "memory")
#define CP_WAIT(n)  asm volatile("cp.async.wait_group %0;" :: "n"(n) : "memory")

// ============================ GroupNorm =====================================
__global__ void __launch_bounds__(256) gn_kernel(const float* __restrict__ x,
                                                 const float* __restrict__ w,
                                                 const float* __restrict__ bg,
                                                 float* __restrict__ h)
{
    const int g = blockIdx.x, b = blockIdx.y;
    const size_t base = ((size_t)b * CC + (size_t)g * CPG) * NN;
    const float* xp = x + base;
    float* hp = h + base;
    const int tid = threadIdx.x;

    float s = 0.f, ss = 0.f;
#pragma unroll
    for (int t = 0; t < 32; t++) {
        float4 v = *reinterpret_cast<const float4*>(xp + (size_t)(t * 256 + tid) * 4);
        s  += v.x + v.y + v.z + v.w;
        ss += v.x * v.x + v.y * v.y + v.z * v.z + v.w * v.w;
    }
#pragma unroll
    for (int o = 16; o; o >>= 1) {
        s  += __shfl_xor_sync(0xffffffffu, s, o);
        ss += __shfl_xor_sync(0xffffffffu, ss, o);
    }
    __shared__ float rs[8], rss[8], stats[2];
    if ((tid & 31) == 0) { rs[tid >> 5] = s; rss[tid >> 5] = ss; }
    __syncthreads();
    if (tid == 0) {
        float ts = 0.f, tss = 0.f;
#pragma unroll
        for (int i = 0; i < 8; i++) { ts += rs[i]; tss += rss[i]; }
        const float inv_n = 1.0f / (CPG * NN);
        float mu = ts * inv_n;
        float var = tss * inv_n - mu * mu;
        stats[0] = mu;
        stats[1] = rsqrtf(var + 1e-5f);
    }
    __syncthreads();
    const float mu = stats[0], rsg = stats[1];
#pragma unroll
    for (int t = 0; t < 32; t++) {
        const int idx = (t * 256 + tid) * 4;
        const int c = g * CPG + (idx >> 12);
        const float sc = w[c] * rsg;
        const float sh = bg[c] - mu * sc;
        float4 v = *reinterpret_cast<const float4*>(xp + idx);
        v.x = v.x * sc + sh; v.y = v.y * sc + sh;
        v.z = v.z * sc + sh; v.w = v.w * sc + sh;
        *reinterpret_cast<float4*>(hp + idx) = v;
    }
}

// =================== weight fp32 -> bf16 convert ============================
__global__ void __launch_bounds__(256) wconv_kernel(const float* __restrict__ qkvw,
                                                    const float* __restrict__ projw,
                                                    __nv_bfloat16* __restrict__ wq,
                                                    __nv_bfloat16* __restrict__ wp)
{
    int idx = blockIdx.x * 256 + threadIdx.x;
    if (idx < 768 * 256) wq[idx] = __float2bfloat16(qkvw[idx]);
    else                 wp[idx - 768 * 256] = __float2bfloat16(projw[idx - 768 * 256]);
}

// ========== h fp32 [b][c][n] -> bf16 [b][n][c] transpose ====================
__global__ void __launch_bounds__(256) ht_kernel(const float* __restrict__ h,
                                                 __nv_bfloat16* __restrict__ ht)
{
    __shared__ float tile[32][33];
    const int b = blockIdx.z;
    const int n0 = blockIdx.x * 32, c0 = blockIdx.y * 32;
    const int tx = threadIdx.x & 31, ty = threadIdx.x >> 5;   // 32 x 8

    const float* src = h + (size_t)b * CC * NN;
#pragma unroll
    for (int i = 0; i < 4; i++) {
        int c = c0 + ty + i * 8;
        tile[ty + i * 8][tx] = src[(size_t)c * NN + n0 + tx];
    }
    __syncthreads();
#pragma unroll
    for (int i = 0; i < 4; i++) {
        int n = n0 + ty + i * 8;
        ht[((size_t)b * NN + n) * CC + c0 + tx] = __float2bfloat16(tile[tx][ty + i * 8]);
    }
}

// ================= bf16 tensor GEMM (qkv mode 0 / proj mode 1) ==============
#define TG_ST  528
#define TG_SA  0
#define TG_SB  (64 * TG_ST)
#define TG_SMEM ((64 + 128) * TG_ST)

__global__ void __launch_bounds__(256) tgemm_kernel(const __nv_bfloat16* __restrict__ A,
                                                    const __nv_bfloat16* __restrict__ Bm,
                                                    const float* __restrict__ bias,
                                                    const float* __restrict__ resid,
                                                    __nv_bfloat16* __restrict__ oq,
                                                    __nv_bfloat16* __restrict__ ok,
                                                    __nv_bfloat16* __restrict__ ov,
                                                    float* __restrict__ ofp,
                                                    int mode)
{
    extern __shared__ char sm[];
    const uint32_t sbase = smem_u32(sm);
    const int tid  = threadIdx.x;
    const int lane = tid & 31;
    const int wid  = tid >> 5;
    const int g    = lane >> 2;
    const int t    = lane & 3;
    const int n0   = blockIdx.x * 128;
    const int m0   = blockIdx.y * 64;
    const int b    = blockIdx.z;

    const __nv_bfloat16* Bb = Bm + (size_t)b * NN * CC;

#pragma unroll
    for (int tt = 0; tt < 8; tt++) {
        int idx = tid + tt * 256;
        int r = idx >> 5, ch = idx & 31;
        CP_ASYNC16(sbase + TG_SA + r * TG_ST + ch * 16,
                   A + (size_t)(m0 + r) * 256 + ch * 8);
    }
#pragma unroll
    for (int tt = 0; tt < 16; tt++) {
        int idx = tid + tt * 256;
        int r = idx >> 5, ch = idx & 31;
        CP_ASYNC16(sbase + TG_SB + r * TG_ST + ch * 16,
                   Bb + (size_t)(n0 + r) * 256 + ch * 8);
    }
    CP_COMMIT();
    CP_WAIT(0);
    __syncthreads();

    const int wm = (wid & 3) * 16;
    const int wn = (wid >> 2) * 64;
    const int lrow = ((lane >> 3) & 1) * 8 + (lane & 7);
    const int loff = ((lane >> 4) & 1) * 16;
    const uint32_t aA = sbase + TG_SA + (wm + lrow) * TG_ST + loff;
    const uint32_t bB = sbase + TG_SB + (wn + lrow) * TG_ST + loff;

    float4 d[8];
#pragma unroll
    for (int j = 0; j < 8; j++) d[j] = make_float4(0.f, 0.f, 0.f, 0.f);

#pragma unroll 4
    for (int kc = 0; kc < 16; kc++) {
        uint32_t a0, a1, a2, a3;
        ldsm_x4(a0, a1, a2, a3, aA + kc * 32);
#pragma unroll
        for (int f = 0; f < 4; f++) {
            uint32_t b0, b1, b2, b3;
            ldsm_x4(b0, b1, b2, b3, bB + f * (16 * TG_ST) + kc * 32);
            mma_bf16(d[2 * f],     a0, a1, a2, a3, b0, b2);
            mma_bf16(d[2 * f + 1], a0, a1, a2, a3, b1, b3);
        }
    }

    const float bv0 = bias[m0 + wm + g];
    const float bv1 = bias[m0 + wm + g + 8];

    if (mode == 1) {
        const int o0 = m0 + wm + g, o1 = o0 + 8;
#pragma unroll
        for (int j = 0; j < 8; j++) {
            const int n = n0 + wn + (j >> 1) * 16 + (j & 1) * 8 + 2 * t;
            const float* r0p = resid + ((size_t)b * CC + o0) * NN + n;
            const float* r1p = resid + ((size_t)b * CC + o1) * NN + n;
            float2 rv0 = *reinterpret_cast<const float2*>(r0p);
            float2 rv1 = *reinterpret_cast<const float2*>(r1p);
            float2 w0 = make_float2(d[j].x + bv0 + rv0.x, d[j].y + bv0 + rv0.y);
            float2 w1 = make_float2(d[j].z + bv1 + rv1.x, d[j].w + bv1 + rv1.y);
            *reinterpret_cast<float2*>(ofp + ((size_t)b * CC + o0) * NN + n) = w0;
            *reinterpret_cast<float2*>(ofp + ((size_t)b * CC + o1) * NN + n) = w1;
        }
        return;
    }

    if (m0 >= 512) {
        const int o0 = m0 - 512 + wm + g, o1 = o0 + 8;
#pragma unroll
        for (int j = 0; j < 8; j++) {
            const int n = n0 + wn + (j >> 1) * 16 + (j & 1) * 8 + 2 * t;
            *reinterpret_cast<uint32_t*>(ov + ((size_t)b * CC + o0) * NN + n) =
                pack_bf16x2(d[j].x + bv0, d[j].y + bv0);
            *reinterpret_cast<uint32_t*>(ov + ((size_t)b * CC + o1) * NN + n) =
                pack_bf16x2(d[j].z + bv1, d[j].w + bv1);
        }
        return;
    }

    const float scl = (m0 < 256) ? 0.09016844f : 1.0f;    // log2(e)/16 for q
    __nv_bfloat16* sT = reinterpret_cast<__nv_bfloat16*>(sm);   // [128 n][72]
    __syncthreads();
    {
        const int m_lo = wm + g, m_hi = m_lo + 8;
#pragma unroll
        for (int j = 0; j < 8; j++) {
            const int n = wn + (j >> 1) * 16 + (j & 1) * 8 + 2 * t;
            sT[n * 72 + m_lo]       = __float2bfloat16((d[j].x + bv0) * scl);
            sT[(n + 1) * 72 + m_lo] = __float2bfloat16((d[j].y + bv0) * scl);
            sT[n * 72 + m_hi]       = __float2bfloat16((d[j].z + bv1) * scl);
            sT[(n + 1) * 72 + m_hi] = __float2bfloat16((d[j].w + bv1) * scl);
        }
    }
    __syncthreads();
    __nv_bfloat16* dst = (m0 < 256) ? oq : ok;
    const int mo = (m0 < 256) ? m0 : m0 - 256;
#pragma unroll
    for (int cidx = 0; cidx < 4; cidx++) {
        int idx = tid + cidx * 256;
        int n = idx >> 3, seg = idx & 7;
        uint4 v = *reinterpret_cast<uint4*>(sT + n * 72 + seg * 8);
        *reinterpret_cast<uint4*>(dst + ((size_t)b * NN + n0 + n) * CC + mo + seg * 8) = v;
    }
}

// ======= flash attention: warp-specialized S/O pipeline (bf16 mma) ==========
// CTA: 64 q, 8 warps. Warps 0-3 (S): S = Q K^T (16q x 64k), softmax, write
// P/alpha to smem. Warps 4-7 (O): O += P(kt-1) V(kt-1)^T (16q x 256c).
// TWO barriers/iter: top barrier (after cp.async wait) makes tile data + P
// visible; bottom barrier closes all reads of the buffers BEFORE the next
// iteration's cp.async prefetch overwrites them (the missing bottom barrier
// was the R16 race). K/V/P/alpha double-buffered.
// cp.async groups: prologue G0={K0}; iter i commits G(i+1)={K(i+1),V(i)};
// wait_group(1) at iter i => K(i), V(i-1) resident.
#define QSTB 528
#define VSTB 144
#define A7_SQ 0                            // 64 x 528            = 33792
#define A7_SK 33792                        // 2 x 64 x 528        -> 101376
#define A7_SKB 33792
#define A7_SV 101376                       // 2 x 256 x 144       -> 175104
#define A7_SVB 36864
#define A7_SP 175104                       // 2 x 64 x 144        -> 193536
#define A7_SPB 9216
#define A7_SAL 193536                      // 2 x 64 floats       -> 194048
#define A7_SL  194048                      // 64 floats           -> 194304
#define A7_SMEM 194304

__global__ void __launch_bounds__(256, 1) attn7_kernel(const __nv_bfloat16* __restrict__ qb,
                                                       const __nv_bfloat16* __restrict__ kb,
                                                       const __nv_bfloat16* __restrict__ vb,
                                                       __nv_bfloat16* __restrict__ ob)
{
    extern __shared__ char sm[];
    const uint32_t sbase = smem_u32(sm);

    const int tid  = threadIdx.x;
    const int lane = tid & 31;
    const int wid  = tid >> 5;
    const int g    = lane >> 2;
    const int t    = lane & 3;
    const int b    = blockIdx.y;
    const int q0   = blockIdx.x * 64;
    const bool is_s = (wid < 4);
    const int qg   = is_s ? wid : (wid - 4);

    const __nv_bfloat16* Qg = qb + ((size_t)b * NN + q0) * 256;
    const __nv_bfloat16* Kg = kb + (size_t)b * NN * 256;
    const __nv_bfloat16* Vg = vb + (size_t)b * CC * NN;

    // ---- load Q tile [64][256] (2048 16B chunks / 256 thr = 8) ----
#pragma unroll
    for (int tt = 0; tt < 8; tt++) {
        int idx = tid + tt * 256;
        int r = idx >> 5, ch = idx & 31;
        *reinterpret_cast<uint4*>(sm + A7_SQ + r * QSTB + ch * 16) =
            *reinterpret_cast<const uint4*>(Qg + (size_t)r * 256 + ch * 8);
    }

    const int kr = tid >> 5, kch = tid & 31;      // K rows kr + tt*8
    const int vc = tid >> 3, vch = tid & 7;       // V rows vc + tt*32

    // prologue: G0 = {K(0)}
    {
        const uint32_t kd = sbase + A7_SK;
#pragma unroll
        for (int tt = 0; tt < 8; tt++) {
            int r = kr + tt * 8;
            CP_ASYNC16(kd + r * QSTB + kch * 16, Kg + (size_t)r * 256 + kch * 8);
        }
        CP_COMMIT();
    }

    const int lrow = ((lane >> 3) & 1) * 8 + (lane & 7);
    const int loff = ((lane >> 4) & 1) * 16;
    const uint32_t aQ = sbase + A7_SQ + (qg * 16 + lrow) * QSTB + loff;

    // S-warp state
    float m0r = -1e30f, m1r = -1e30f, l0r = 0.f, l1r = 0.f;
    // O-warp state
    float4 oacc[32];
#pragma unroll
    for (int j = 0; j < 32; j++) oacc[j] = make_float4(0.f, 0.f, 0.f, 0.f);

    for (int i = 0; i < 64; i++) {
        const int cur = i & 1;
        // prefetch G(i+1) = {K(i+1) [if any], V(i)} — safe: the bottom barrier
        // of iter i-1 closed all reads of the target buffers.
        {
            if (i < 63) {
                const int k0n = (i + 1) * 64;
                const uint32_t kd = sbase + A7_SK + ((i + 1) & 1) * A7_SKB;
#pragma unroll
                for (int tt = 0; tt < 8; tt++) {
                    int r = kr + tt * 8;
                    CP_ASYNC16(kd + r * QSTB + kch * 16,
                               Kg + (size_t)(k0n + r) * 256 + kch * 8);
                }
            }
            const int k0 = i * 64;
            const uint32_t vd = sbase + A7_SV + cur * A7_SVB;
#pragma unroll
            for (int tt = 0; tt < 8; tt++) {
                int c = vc + tt * 32;
                CP_ASYNC16(vd + c * VSTB + vch * 16,
                           Vg + (size_t)c * NN + k0 + vch * 8);
            }
            CP_COMMIT();
            CP_WAIT(1);                     // K(i), V(i-1) resident
        }
        __syncthreads();                    // (top) tile data + P(i-1)/alpha visible

        if (is_s) {
            // ---- S = Q K(i)^T : 16q x 64k ----
            const uint32_t bK = sbase + A7_SK + cur * A7_SKB + lrow * QSTB + loff;
            float4 d[8];
#pragma unroll
            for (int j = 0; j < 8; j++) d[j] = make_float4(0.f, 0.f, 0.f, 0.f);
#pragma unroll 4
            for (int kc = 0; kc < 16; kc++) {
                uint32_t a0, a1, a2, a3;
                ldsm_x4(a0, a1, a2, a3, aQ + kc * 32);
#pragma unroll
                for (int ng = 0; ng < 4; ng++) {
                    uint32_t b0, b1, b2, b3;
                    ldsm_x4(b0, b1, b2, b3, bK + ng * (16 * QSTB) + kc * 32);
                    mma_bf16(d[2 * ng],     a0, a1, a2, a3, b0, b2);
                    mma_bf16(d[2 * ng + 1], a0, a1, a2, a3, b1, b3);
                }
            }

            // ---- online softmax (log2 units) ----
            float nm0 = -1e30f, nm1 = -1e30f;
#pragma unroll
            for (int j = 0; j < 8; j++) {
                nm0 = fmaxf(nm0, fmaxf(d[j].x, d[j].y));
                nm1 = fmaxf(nm1, fmaxf(d[j].z, d[j].w));
            }
            nm0 = fmaxf(nm0, __shfl_xor_sync(0xffffffffu, nm0, 1));
            nm0 = fmaxf(nm0, __shfl_xor_sync(0xffffffffu, nm0, 2));
            nm1 = fmaxf(nm1, __shfl_xor_sync(0xffffffffu, nm1, 1));
            nm1 = fmaxf(nm1, __shfl_xor_sync(0xffffffffu, nm1, 2));
            nm0 = fmaxf(m0r, nm0);
            nm1 = fmaxf(m1r, nm1);
            const float al0 = ex2f(m0r - nm0);
            const float al1 = ex2f(m1r - nm1);
            m0r = nm0; m1r = nm1;

            char* Pb = sm + A7_SP + cur * A7_SPB;
            float ls0 = 0.f, ls1 = 0.f;
#pragma unroll
            for (int kc = 0; kc < 4; kc++) {
                float p00 = ex2f(d[2 * kc].x - nm0), p01 = ex2f(d[2 * kc].y - nm0);
                float p02 = ex2f(d[2 * kc].z - nm1), p03 = ex2f(d[2 * kc].w - nm1);
                float p10 = ex2f(d[2 * kc + 1].x - nm0), p11 = ex2f(d[2 * kc + 1].y - nm0);
                float p12 = ex2f(d[2 * kc + 1].z - nm1), p13 = ex2f(d[2 * kc + 1].w - nm1);
                ls0 += (p00 + p01) + (p10 + p11);
                ls1 += (p02 + p03) + (p12 + p13);
                const int c0b = (kc * 16 + 2 * t) * 2;
                const int c1b = (kc * 16 + 8 + 2 * t) * 2;
                *reinterpret_cast<uint32_t*>(Pb + (qg * 16 + g) * VSTB + c0b)     = pack_bf16x2(p00, p01);
                *reinterpret_cast<uint32_t*>(Pb + (qg * 16 + g + 8) * VSTB + c0b) = pack_bf16x2(p02, p03);
                *reinterpret_cast<uint32_t*>(Pb + (qg * 16 + g) * VSTB + c1b)     = pack_bf16x2(p10, p11);
                *reinterpret_cast<uint32_t*>(Pb + (qg * 16 + g + 8) * VSTB + c1b) = pack_bf16x2(p12, p13);
            }
            l0r = l0r * al0 + ls0;
            l1r = l1r * al1 + ls1;
            if (t == 0) {
                float* Ab = reinterpret_cast<float*>(sm + A7_SAL + cur * 256);
                Ab[qg * 16 + g]     = al0;
                Ab[qg * 16 + g + 8] = al1;
            }
        } else if (i > 0) {
            // ---- O += P(i-1) V(i-1)^T : 16q x 256c ----
            const int prev = (i - 1) & 1;
            const float* Ab = reinterpret_cast<const float*>(sm + A7_SAL + prev * 256);
            const float al0 = Ab[qg * 16 + g];
            const float al1 = Ab[qg * 16 + g + 8];
            if (!__all_sync(0xffffffffu, (al0 == 1.f) & (al1 == 1.f))) {
#pragma unroll
                for (int j = 0; j < 32; j++) {
                    oacc[j].x *= al0; oacc[j].y *= al0;
                    oacc[j].z *= al1; oacc[j].w *= al1;
                }
            }
            const uint32_t aP = sbase + A7_SP + prev * A7_SPB + (qg * 16 + lrow) * VSTB + loff;
            uint32_t pf[4][4];
#pragma unroll
            for (int kc = 0; kc < 4; kc++)
                ldsm_x4(pf[kc][0], pf[kc][1], pf[kc][2], pf[kc][3], aP + kc * 32);
            const uint32_t bV = sbase + A7_SV + prev * A7_SVB + lrow * VSTB + loff;
#pragma unroll 4
            for (int cg = 0; cg < 16; cg++) {
#pragma unroll
                for (int kc = 0; kc < 4; kc++) {
                    uint32_t b0, b1, b2, b3;
                    ldsm_x4(b0, b1, b2, b3, bV + cg * (16 * VSTB) + kc * 32);
                    mma_bf16(oacc[2 * cg],     pf[kc][0], pf[kc][1], pf[kc][2], pf[kc][3], b0, b2);
                    mma_bf16(oacc[2 * cg + 1], pf[kc][0], pf[kc][1], pf[kc][2], pf[kc][3], b1, b3);
                }
            }
        }
        __syncthreads();                    // (bottom) all reads closed before
    }                                       // next iteration's prefetch

    // ---- S-warps: finalize l and publish ----
    if (is_s) {
        l0r += __shfl_xor_sync(0xffffffffu, l0r, 1);
        l0r += __shfl_xor_sync(0xffffffffu, l0r, 2);
        l1r += __shfl_xor_sync(0xffffffffu, l1r, 1);
        l1r += __shfl_xor_sync(0xffffffffu, l1r, 2);
        if (t == 0) {
            float* Lb = reinterpret_cast<float*>(sm + A7_SL);
            Lb[qg * 16 + g]     = l0r;
            Lb[qg * 16 + g + 8] = l1r;
        }
    }
    CP_WAIT(0);                             // V(63) resident
    __syncthreads();                        // P(63), alpha(63), l visible

    if (!is_s) {
        // ---- final accumulation: tile 63 ----
        const int prev = 63 & 1;
        const float* Ab = reinterpret_cast<const float*>(sm + A7_SAL + prev * 256);
        const float al0 = Ab[qg * 16 + g];
        const float al1 = Ab[qg * 16 + g + 8];
        if (!__all_sync(0xffffffffu, (al0 == 1.f) & (al1 == 1.f))) {
#pragma unroll
            for (int j = 0; j < 32; j++) {
                oacc[j].x *= al0; oacc[j].y *= al0;
                oacc[j].z *= al1; oacc[j].w *= al1;
            }
        }
        const uint32_t aP = sbase + A7_SP + prev * A7_SPB + (qg * 16 + lrow) * VSTB + loff;
        uint32_t pf[4][4];
#pragma unroll
        for (int kc = 0; kc < 4; kc++)
            ldsm_x4(pf[kc][0], pf[kc][1], pf[kc][2], pf[kc][3], aP + kc * 32);
        const uint32_t bV = sbase + A7_SV + prev * A7_SVB + lrow * VSTB + loff;
#pragma unroll 4
        for (int cg = 0; cg < 16; cg++) {
#pragma unroll
            for (int kc = 0; kc < 4; kc++) {
                uint32_t b0, b1, b2, b3;
                ldsm_x4(b0, b1, b2, b3, bV + cg * (16 * VSTB) + kc * 32);
                mma_bf16(oacc[2 * cg],     pf[kc][0], pf[kc][1], pf[kc][2], pf[kc][3], b0, b2);
                mma_bf16(oacc[2 * cg + 1], pf[kc][0], pf[kc][1], pf[kc][2], pf[kc][3], b1, b3);
            }
        }

        // ---- epilogue: O / l -> bf16 [b][n][c] ----
        const float* Lb = reinterpret_cast<const float*>(sm + A7_SL);
        const float inv0 = __frcp_rn(Lb[qg * 16 + g]);
        const float inv1 = __frcp_rn(Lb[qg * 16 + g + 8]);
        const int qr0 = q0 + qg * 16 + g;
        const int qr1 = qr0 + 8;
        __nv_bfloat16* r0p = ob + ((size_t)b * NN + qr0) * CC;
        __nv_bfloat16* r1p = ob + ((size_t)b * NN + qr1) * CC;
#pragma unroll
        for (int j = 0; j < 32; j++) {
            const int c = 8 * j + t * 2;
            *reinterpret_cast<uint32_t*>(r0p + c) =
                pack_bf16x2(oacc[j].x * inv0, oacc[j].y * inv0);
            *reinterpret_cast<uint32_t*>(r1p + c) =
                pack_bf16x2(oacc[j].z * inv1, oacc[j].w * inv1);
        }
    }
}

// ================================ launch ====================================
extern "C" void kernel_launch(void* const* d_in, const int* in_sizes, int n_in,
                              void* d_out, int out_size)
{
    const float* x     = (const float*)d_in[0];
    const float* nw    = (const float*)d_in[1];
    const float* nb    = (const float*)d_in[2];
    const float* qkvw  = (const float*)d_in[3];
    const float* qkvb  = (const float*)d_in[4];
    const float* projw = (const float*)d_in[5];
    const float* projb = (const float*)d_in[6];
    float* out = (float*)d_out;

    float* hbuf;
    __nv_bfloat16 *htp, *wqp, *wpp, *qbp, *kbp, *vbp, *obp;
    cudaGetSymbolAddress((void**)&hbuf, g_h);
    cudaGetSymbolAddress((void**)&htp, g_ht);
    cudaGetSymbolAddress((void**)&wqp, g_wq);
    cudaGetSymbolAddress((void**)&wpp, g_wp);
    cudaGetSymbolAddress((void**)&qbp, g_qb);
    cudaGetSymbolAddress((void**)&kbp, g_kb);
    cudaGetSymbolAddress((void**)&vbp, g_vb);
    cudaGetSymbolAddress((void**)&obp, g_ob);

    cudaFuncSetAttribute(attn7_kernel, cudaFuncAttributeMaxDynamicSharedMemorySize,
                         A7_SMEM);
    cudaFuncSetAttribute(tgemm_kernel, cudaFuncAttributeMaxDynamicSharedMemorySize,
                         TG_SMEM);

    gn_kernel<<<dim3(GG, BB), 256>>>(x, nw, nb, hbuf);
    wconv_kernel<<<(768 * 256 + 256 * 256) / 256, 256>>>(qkvw, projw, wqp, wpp);
    ht_kernel<<<dim3(NN / 32, CC / 32, BB), 256>>>(hbuf, htp);
    tgemm_kernel<<<dim3(NN / 128, 12, BB), 256, TG_SMEM>>>(
        wqp, htp, qkvb, nullptr, qbp, kbp, vbp, nullptr, 0);
    attn7_kernel<<<dim3(NN / 64, BB), 256, A7_SMEM>>>(qbp, kbp, vbp, obp);
    tgemm_kernel<<<dim3(NN / 128, 4, BB), 256, TG_SMEM>>>(
        wpp, obp, projb, x, nullptr, nullptr, nullptr, out, 1);
}